// round 9
// baseline (speedup 1.0000x reference)
#include <cuda_runtime.h>
#include <cstddef>

#define NPTS 50000
#define C    96
#define G    6
#define S    16

typedef unsigned long long u64;

// packed fp32x2 helpers -------------------------------------------------------
__device__ __forceinline__ u64 fma2(u64 a, u64 b, u64 c) {
    u64 d;
    asm("fma.rn.f32x2 %0, %1, %2, %3;" : "=l"(d) : "l"(a), "l"(b), "l"(c));
    return d;
}
__device__ __forceinline__ float lo2(u64 v) { return __uint_as_float((unsigned)v); }
__device__ __forceinline__ float hi2(u64 v) { return __uint_as_float((unsigned)(v >> 32)); }
__device__ __forceinline__ float hsum2(u64 v) { return lo2(v) + hi2(v); }

// ---------------- scratch (static device globals) ----------------------------
__device__ float d_v   [NPTS * C];
__device__ float d_qW  [NPTS * G];
__device__ float d_kW  [NPTS * G];
__device__ float d_MT  [G * C];      // [g][cc] = (Wp2 @ Ww1)[cc][g]
__device__ float d_bM  [G];          // bp2 @ Ww1
__device__ float d_Wp2T[C * C];      // [co][ci]

// ---------------- k1: persistent QKV projections + qW/kW ---------------------
#define K1_TILE 64
#define K1_THREADS 256
#define K1_GRID 304
#define K1_TILES ((NPTS + K1_TILE - 1) / K1_TILE)
#define K1_SMEM_F (K1_TILE*100 + C*100 + K1_TILE*100 + G*100)
#define K1_SMEM (K1_SMEM_F * 4)

__global__ __launch_bounds__(K1_THREADS, 2)
void k1_qkv(const float* __restrict__ feat,
            const float* __restrict__ Wq, const float* __restrict__ bq,
            const float* __restrict__ gq, const float* __restrict__ betaq,
            const float* __restrict__ Wk, const float* __restrict__ bk,
            const float* __restrict__ gk, const float* __restrict__ betak,
            const float* __restrict__ Wv, const float* __restrict__ bv,
            const float* __restrict__ Ww1,
            const float* __restrict__ Wp2, const float* __restrict__ bp2)
{
    const int tid = threadIdx.x;

    if (blockIdx.x == 0) {   // precompute for k2
        for (int i = tid; i < C * C; i += K1_THREADS) {
            int co = i / C, ci = i % C;
            d_Wp2T[i] = __ldg(&Wp2[ci * C + co]);
        }
        for (int i = tid; i < G * C; i += K1_THREADS) {
            int g = i / C, cc = i % C;
            float s = 0.f;
            #pragma unroll 4
            for (int c2 = 0; c2 < C; c2++)
                s = fmaf(__ldg(&Wp2[cc * C + c2]), __ldg(&Ww1[c2 * G + g]), s);
            d_MT[i] = s;
        }
        if (tid < G) {
            float s = 0.f;
            for (int c2 = 0; c2 < C; c2++)
                s = fmaf(__ldg(&bp2[c2]), __ldg(&Ww1[c2 * G + tid]), s);
            d_bM[tid] = s;
        }
    }

    extern __shared__ float sh[];
    float* featS = sh;                        // [p][k] stride 100
    float* WST   = sh + K1_TILE * 100;        // [c][k] stride 100
    float* tmpS  = WST + C * 100;             // [p][c] stride 100
    float* Ww1T  = tmpS + K1_TILE * 100;      // [g][c] stride 100

    const float RS = rsqrtf(1.0f + 1e-5f);
    const int tx = tid & 31, ty = tid >> 5;

    for (int i = tid; i < C * G; i += K1_THREADS) {
        int c2 = i / G, g = i % G;
        Ww1T[g * 100 + c2] = Ww1[i];
    }

    for (int tile = blockIdx.x; tile < K1_TILES; tile += K1_GRID) {
        const int n0 = tile * K1_TILE;

        for (int i = tid; i < K1_TILE * 24; i += K1_THREADS) {
            int p = i / 24, kq = (i % 24) * 4;
            int n = n0 + p;
            float4 vv = (n < NPTS) ? *(const float4*)&feat[(size_t)n * C + kq]
                                   : make_float4(0.f, 0.f, 0.f, 0.f);
            *(float4*)&featS[p * 100 + kq] = vv;
        }

        for (int m = 0; m < 3; m++) {
            __syncthreads();
            const float* W = (m == 0) ? Wq : (m == 1) ? Wk : Wv;
            for (int i = tid; i < C * 24; i += K1_THREADS) {
                int k = i / 24, cq = (i % 24) * 4;
                float4 w = *(const float4*)&W[k * C + cq];
                WST[(cq + 0) * 100 + k] = w.x;
                WST[(cq + 1) * 100 + k] = w.y;
                WST[(cq + 2) * 100 + k] = w.z;
                WST[(cq + 3) * 100 + k] = w.w;
            }
            __syncthreads();

            u64 acc[8][3];
            #pragma unroll
            for (int pp = 0; pp < 8; pp++)
                acc[pp][0] = acc[pp][1] = acc[pp][2] = 0ull;

            #pragma unroll 2
            for (int k4 = 0; k4 < C; k4 += 4) {
                ulonglong2 b0 = *(const ulonglong2*)&WST[tx * 100 + k4];
                ulonglong2 b1 = *(const ulonglong2*)&WST[(tx + 32) * 100 + k4];
                ulonglong2 b2 = *(const ulonglong2*)&WST[(tx + 64) * 100 + k4];
                #pragma unroll
                for (int pp = 0; pp < 8; pp++) {
                    ulonglong2 a = *(const ulonglong2*)&featS[(ty * 8 + pp) * 100 + k4];
                    acc[pp][0] = fma2(a.x, b0.x, acc[pp][0]);
                    acc[pp][0] = fma2(a.y, b0.y, acc[pp][0]);
                    acc[pp][1] = fma2(a.x, b1.x, acc[pp][1]);
                    acc[pp][1] = fma2(a.y, b1.y, acc[pp][1]);
                    acc[pp][2] = fma2(a.x, b2.x, acc[pp][2]);
                    acc[pp][2] = fma2(a.y, b2.y, acc[pp][2]);
                }
            }

            if (m < 2) {
                const float* bb_ = (m == 0) ? bq : bk;
                const float* gg_ = (m == 0) ? gq : gk;
                const float* bt_ = (m == 0) ? betaq : betak;
                float bb[3], sc[3], bt[3];
                #pragma unroll
                for (int cc = 0; cc < 3; cc++) {
                    int ch = tx + 32 * cc;
                    bb[cc] = bb_[ch];
                    sc[cc] = gg_[ch] * RS;
                    bt[cc] = bt_[ch];
                }
                #pragma unroll
                for (int pp = 0; pp < 8; pp++) {
                    int p = ty * 8 + pp;
                    #pragma unroll
                    for (int cc = 0; cc < 3; cc++) {
                        float r = hsum2(acc[pp][cc]);
                        float v = fmaf(r + bb[cc], sc[cc], bt[cc]);
                        tmpS[p * 100 + tx + 32 * cc] = fmaxf(v, 0.f);
                    }
                }
                __syncthreads();
                float* dst = (m == 0) ? d_qW : d_kW;
                for (int t = tid; t < K1_TILE * G; t += K1_THREADS) {
                    int p = t / G, g = t % G;
                    int n = n0 + p;
                    if (n < NPTS) {
                        u64 s2 = 0ull;
                        #pragma unroll
                        for (int c4 = 0; c4 < C; c4 += 4) {
                            ulonglong2 hv = *(const ulonglong2*)&tmpS[p * 100 + c4];
                            ulonglong2 wv = *(const ulonglong2*)&Ww1T[g * 100 + c4];
                            s2 = fma2(hv.x, wv.x, s2);
                            s2 = fma2(hv.y, wv.y, s2);
                        }
                        dst[(size_t)n * G + g] = hsum2(s2);
                    }
                }
            } else {
                float bb[3];
                #pragma unroll
                for (int cc = 0; cc < 3; cc++) bb[cc] = bv[tx + 32 * cc];
                #pragma unroll
                for (int pp = 0; pp < 8; pp++) {
                    int p = ty * 8 + pp;
                    #pragma unroll
                    for (int cc = 0; cc < 3; cc++)
                        tmpS[p * 100 + tx + 32 * cc] = hsum2(acc[pp][cc]) + bb[cc];
                }
                __syncthreads();
                for (int i = tid; i < K1_TILE * 24; i += K1_THREADS) {
                    int p = i / 24, cq = (i % 24) * 4;
                    int n = n0 + p;
                    if (n < NPTS)
                        *(float4*)&d_v[(size_t)n * C + cq] = *(const float4*)&tmpS[p * 100 + cq];
                }
            }
        }
        __syncthreads();
    }
}

// ---------------- k2: persistent per-point attention (R4 exact) --------------
#define PTS 4
#define K2_THREADS (PTS * C)      // 384
#define K2_TILES (NPTS / PTS)     // 12500
#define K2_GRID 304
#define POD_F 2608
#define K2_SMEM_F (C*100 + G*100 + 68 + PTS*POD_F)   // 82.8KB
#define K2_SMEM (K2_SMEM_F * 4)

__device__ __forceinline__ void podbar(int pod) {
    asm volatile("bar.sync %0, 96;" :: "r"(pod + 1) : "memory");
}

__global__ __launch_bounds__(K2_THREADS, 2)
void k2_attn(const float* __restrict__ coord,
             const int*   __restrict__ refidx,
             const float* __restrict__ Wp1, const float* __restrict__ bp1,
             const float* __restrict__ gp,  const float* __restrict__ betap,
             const float* __restrict__ bp2,
             const float* __restrict__ bw1, const float* __restrict__ gw,
             const float* __restrict__ betaw,
             const float* __restrict__ Ww2, const float* __restrict__ bw2,
             float* __restrict__ out)
{
    extern __shared__ float sh[];
    float* Wp2T = sh;                  // [co][ci] stride 100
    float* MTs  = sh + C * 100;        // [g][cc] stride 100
    float* cst  = MTs + G * 100;       // Ww2(36) bw2(6) bw1(6) gw(6) betaw(6) bM(6)
    float* podb = cst + 68;

    const int tid = threadIdx.x;
    const int pod = tid / C;
    const int c   = tid % C;

    float* P    = podb + pod * POD_F;
    float* hs   = P;            // [16][100]
    float* Hs   = P + 1600;     // [6][100]
    float* ws   = P + 2200;     // [16][8]
    float* us   = P + 2328;     // [16][6]
    float* wls  = P + 2424;     // [16][6]
    float* pos  = P + 2520;     // [16][4]
    float* wsum = P + 2584;     // [8]
    int*   js   = (int*)(P + 2592);  // [16]

    const float RS = rsqrtf(1.0f + 1e-5f);

    // ---- one-time staging ----
    for (int i = tid; i < C * 24; i += K2_THREADS) {
        int co = i / 24, ciq = (i % 24) * 4;
        *(float4*)&Wp2T[co * 100 + ciq] = *(const float4*)&d_Wp2T[co * C + ciq];
    }
    for (int i = tid; i < G * C; i += K2_THREADS)
        MTs[(i / C) * 100 + (i % C)] = d_MT[i];
    if      (tid < 36) cst[tid] = Ww2[tid];
    else if (tid < 42) cst[tid] = bw2[tid - 36];
    else if (tid < 48) cst[tid] = bw1[tid - 42];
    else if (tid < 54) cst[tid] = gw[tid - 48];
    else if (tid < 60) cst[tid] = betaw[tid - 54];
    else if (tid < 66) cst[tid] = d_bM[tid - 60];
    if (c < S) { ws[c * 8 + 6] = 0.f; ws[c * 8 + 7] = 0.f; }   // pads, zero once

    const float w10  = __ldg(&Wp1[c]);
    const float w11  = __ldg(&Wp1[C + c]);
    const float w12  = __ldg(&Wp1[2 * C + c]);
    const float bp1c = __ldg(&bp1[c]);
    const float sp   = __ldg(&gp[c]) * RS;
    const float btp  = __ldg(&betap[c]);
    const float bp2c = __ldg(&bp2[c]);
    const int   gc   = c >> 4;
    __syncthreads();

    for (int t = blockIdx.x; t < K2_TILES; t += K2_GRID) {
        const int n = t * PTS + pod;

        // P1/P2: indices + relative positions
        if (c < S) js[c] = refidx[(size_t)n * S + c];
        if (c < 48) {
            int s = c / 3, d = c % 3;
            int j = __ldg(&refidx[(size_t)n * S + s]);
            pos[s * 4 + d] = __ldg(&coord[(size_t)j * 3 + d]) - __ldg(&coord[(size_t)n * 3 + d]);
        }
        podbar(pod);

        // P3: h[s][c] = relu(bn(pos@Wp1 + bp1)); keep in regs AND smem
        float hr[16];
        #pragma unroll
        for (int s = 0; s < 16; s++) {
            float px = pos[s * 4], py = pos[s * 4 + 1], pz = pos[s * 4 + 2];
            float hv = fmaf(px, w10, fmaf(py, w11, fmaf(pz, w12, bp1c)));
            hv = fmaxf(fmaf(hv, sp, btp), 0.0f);
            hr[s] = hv;
            hs[s * 100 + c] = hv;
        }
        podbar(pod);

        // P4: u[s][g] = relu(bn(kW[j]-qW[n] + h@M + bM + bw1))
        {
            int s = c / 6, g = c % 6;
            u64 a2 = 0ull;
            #pragma unroll
            for (int c4 = 0; c4 < C; c4 += 4) {
                ulonglong2 hv = *(const ulonglong2*)&hs[s * 100 + c4];
                ulonglong2 mv = *(const ulonglong2*)&MTs[g * 100 + c4];
                a2 = fma2(hv.x, mv.x, a2);
                a2 = fma2(hv.y, mv.y, a2);
            }
            float kq = __ldg(&d_kW[(size_t)js[s] * G + g]) - __ldg(&d_qW[(size_t)n * G + g]);
            float tt = kq + hsum2(a2) + cst[60 + g] + cst[42 + g];
            us[s * 6 + g] = fmaxf(fmaf(tt, cst[48 + g] * RS, cst[54 + g]), 0.0f);
        }
        podbar(pod);

        // P5: logits = u @ Ww2 + bw2
        {
            int s = c / 6, g2 = c % 6;
            float lg = cst[36 + g2];
            #pragma unroll
            for (int g = 0; g < 6; g++) lg = fmaf(us[s * 6 + g], cst[g * 6 + g2], lg);
            wls[s * 6 + g2] = lg;
        }
        podbar(pod);

        // P6: softmax over s per g (6 threads/pod)
        if (c < 6) {
            int g = c;
            float m = -1e30f;
            #pragma unroll
            for (int s = 0; s < 16; s++) m = fmaxf(m, wls[s * 6 + g]);
            float sum = 0.f;
            #pragma unroll
            for (int s = 0; s < 16; s++) sum += __expf(wls[s * 6 + g] - m);
            float inv = 1.0f / sum;
            float accw = 0.f;
            #pragma unroll
            for (int s = 0; s < 16; s++) {
                int jp1 = js[s] + 1;
                float msk = (float)((jp1 > 0) - (jp1 < 0));
                float w = __expf(wls[s * 6 + g] - m) * inv * msk;
                ws[s * 8 + g] = w;
                accw += w;
            }
            wsum[g] = accw;
        }
        podbar(pod);

        // P7: H[g][c] = sum_s w[s][g]*hr[s]; vsum = sum_s w[s][gc]*v[j_s][c]
        float Hg[6] = {0, 0, 0, 0, 0, 0};
        float vsum = 0.f;
        #pragma unroll
        for (int s = 0; s < 16; s++) {
            float4 wa = *(const float4*)&ws[s * 8];
            float4 wb = *(const float4*)&ws[s * 8 + 4];
            float h = hr[s];
            Hg[0] = fmaf(wa.x, h, Hg[0]);
            Hg[1] = fmaf(wa.y, h, Hg[1]);
            Hg[2] = fmaf(wa.z, h, Hg[2]);
            Hg[3] = fmaf(wa.w, h, Hg[3]);
            Hg[4] = fmaf(wb.x, h, Hg[4]);
            Hg[5] = fmaf(wb.y, h, Hg[5]);
            float wg = (gc == 0) ? wa.x : (gc == 1) ? wa.y : (gc == 2) ? wa.z
                     : (gc == 3) ? wa.w : (gc == 4) ? wb.x : wb.y;
            vsum = fmaf(wg, __ldg(&d_v[(size_t)js[s] * C + c]), vsum);
        }
        #pragma unroll
        for (int g = 0; g < 6; g++) Hs[g * 100 + c] = Hg[g];
        podbar(pod);

        // P8: out[c] = vsum + bp2[c]*wsum[gc] + H[gc] . Wp2[:,c]
        {
            u64 a2 = 0ull;
            #pragma unroll
            for (int c4 = 0; c4 < C; c4 += 4) {
                ulonglong2 hh = *(const ulonglong2*)&Hs[gc * 100 + c4];
                ulonglong2 wv = *(const ulonglong2*)&Wp2T[c * 100 + c4];
                a2 = fma2(hh.x, wv.x, a2);
                a2 = fma2(hh.y, wv.y, a2);
            }
            out[(size_t)n * C + c] = fmaf(bp2c, wsum[gc], vsum) + hsum2(a2);
        }
        podbar(pod);   // protect pod buffers before next tile's writes
    }
}

// ---------------- host launcher ---------------------------------------------
extern "C" void kernel_launch(void* const* d_in, const int* in_sizes, int n_in,
                              void* d_out, int out_size)
{
    bool dict = (in_sizes[2] == NPTS * S);

    const float* feat  = (const float*)d_in[0];
    const float* coord = (const float*)d_in[1];
    const int*   ref   = (const int*)d_in[dict ? 2 : 24];
    int wb = dict ? 3 : 2;
    const float* Wq    = (const float*)d_in[wb + 0];
    const float* bq    = (const float*)d_in[wb + 1];
    const float* gq    = (const float*)d_in[wb + 2];
    const float* betaq = (const float*)d_in[wb + 3];
    const float* Wk    = (const float*)d_in[wb + 4];
    const float* bk    = (const float*)d_in[wb + 5];
    const float* gk    = (const float*)d_in[wb + 6];
    const float* betak = (const float*)d_in[wb + 7];
    const float* Wv    = (const float*)d_in[wb + 8];
    const float* bv    = (const float*)d_in[wb + 9];
    const float* Wp1   = (const float*)d_in[wb + 10];
    const float* bp1   = (const float*)d_in[wb + 11];
    const float* gp    = (const float*)d_in[wb + 12];
    const float* betap = (const float*)d_in[wb + 13];
    const float* Wp2   = (const float*)d_in[wb + 14];
    const float* bp2   = (const float*)d_in[wb + 15];
    const float* Ww1   = (const float*)d_in[wb + 16];
    const float* bw1   = (const float*)d_in[wb + 17];
    const float* gw    = (const float*)d_in[wb + 18];
    const float* betaw = (const float*)d_in[wb + 19];
    const float* Ww2   = (const float*)d_in[wb + 20];
    const float* bw2   = (const float*)d_in[wb + 21];
    float* out = (float*)d_out;

    cudaFuncSetAttribute(k1_qkv,  cudaFuncAttributeMaxDynamicSharedMemorySize, K1_SMEM);
    cudaFuncSetAttribute(k2_attn, cudaFuncAttributeMaxDynamicSharedMemorySize, K2_SMEM);

    k1_qkv<<<K1_GRID, K1_THREADS, K1_SMEM>>>(
        feat, Wq, bq, gq, betaq, Wk, bk, gk, betak, Wv, bv, Ww1, Wp2, bp2);
    k2_attn<<<K2_GRID, K2_THREADS, K2_SMEM>>>(
        coord, ref, Wp1, bp1, gp, betap, bp2, bw1, gw, betaw, Ww2, bw2, out);
}

// round 10
// speedup vs baseline: 1.3303x; 1.3303x over previous
#include <cuda_runtime.h>
#include <cstddef>

#define NPTS 50000
#define C    96
#define G    6
#define S    16

typedef unsigned long long u64;

// packed fp32x2 helpers -------------------------------------------------------
__device__ __forceinline__ u64 fma2(u64 a, u64 b, u64 c) {
    u64 d;
    asm("fma.rn.f32x2 %0, %1, %2, %3;" : "=l"(d) : "l"(a), "l"(b), "l"(c));
    return d;
}
__device__ __forceinline__ float lo2(u64 v) { return __uint_as_float((unsigned)v); }
__device__ __forceinline__ float hi2(u64 v) { return __uint_as_float((unsigned)(v >> 32)); }
__device__ __forceinline__ float hsum2(u64 v) { return lo2(v) + hi2(v); }
__device__ __forceinline__ u64 dup2(float x) {
    u64 r;
    asm("mov.b64 %0, {%1, %1};" : "=l"(r) : "r"(__float_as_uint(x)));
    return r;
}

// ---------------- scratch (static device globals) ----------------------------
__device__ float d_v   [NPTS * C];
__device__ float d_qW  [NPTS * G];
__device__ float d_kW  [NPTS * G];
__device__ float d_MT  [G * C];      // [g][cc] = (Wp2 @ Ww1)[cc][g]
__device__ float d_bM  [G];          // bp2 @ Ww1
__device__ float d_Wp2T[C * C];      // [co][ci]

// ---------------- k1: persistent QKV projections + qW/kW (unchanged) ---------
#define K1_TILE 64
#define K1_THREADS 256
#define K1_GRID 304
#define K1_TILES ((NPTS + K1_TILE - 1) / K1_TILE)
#define K1_SMEM_F (K1_TILE*100 + C*100 + K1_TILE*100 + G*100)
#define K1_SMEM (K1_SMEM_F * 4)

__global__ __launch_bounds__(K1_THREADS, 2)
void k1_qkv(const float* __restrict__ feat,
            const float* __restrict__ Wq, const float* __restrict__ bq,
            const float* __restrict__ gq, const float* __restrict__ betaq,
            const float* __restrict__ Wk, const float* __restrict__ bk,
            const float* __restrict__ gk, const float* __restrict__ betak,
            const float* __restrict__ Wv, const float* __restrict__ bv,
            const float* __restrict__ Ww1,
            const float* __restrict__ Wp2, const float* __restrict__ bp2)
{
    const int tid = threadIdx.x;

    if (blockIdx.x == 0) {   // precompute for k2
        for (int i = tid; i < C * C; i += K1_THREADS) {
            int co = i / C, ci = i % C;
            d_Wp2T[i] = __ldg(&Wp2[ci * C + co]);
        }
        for (int i = tid; i < G * C; i += K1_THREADS) {
            int g = i / C, cc = i % C;
            float s = 0.f;
            #pragma unroll 4
            for (int c2 = 0; c2 < C; c2++)
                s = fmaf(__ldg(&Wp2[cc * C + c2]), __ldg(&Ww1[c2 * G + g]), s);
            d_MT[i] = s;
        }
        if (tid < G) {
            float s = 0.f;
            for (int c2 = 0; c2 < C; c2++)
                s = fmaf(__ldg(&bp2[c2]), __ldg(&Ww1[c2 * G + tid]), s);
            d_bM[tid] = s;
        }
    }

    extern __shared__ float sh[];
    float* featS = sh;                        // [p][k] stride 100
    float* WST   = sh + K1_TILE * 100;        // [c][k] stride 100
    float* tmpS  = WST + C * 100;             // [p][c] stride 100
    float* Ww1T  = tmpS + K1_TILE * 100;      // [g][c] stride 100

    const float RS = rsqrtf(1.0f + 1e-5f);
    const int tx = tid & 31, ty = tid >> 5;

    for (int i = tid; i < C * G; i += K1_THREADS) {
        int c2 = i / G, g = i % G;
        Ww1T[g * 100 + c2] = Ww1[i];
    }

    for (int tile = blockIdx.x; tile < K1_TILES; tile += K1_GRID) {
        const int n0 = tile * K1_TILE;

        for (int i = tid; i < K1_TILE * 24; i += K1_THREADS) {
            int p = i / 24, kq = (i % 24) * 4;
            int n = n0 + p;
            float4 vv = (n < NPTS) ? *(const float4*)&feat[(size_t)n * C + kq]
                                   : make_float4(0.f, 0.f, 0.f, 0.f);
            *(float4*)&featS[p * 100 + kq] = vv;
        }

        for (int m = 0; m < 3; m++) {
            __syncthreads();
            const float* W = (m == 0) ? Wq : (m == 1) ? Wk : Wv;
            for (int i = tid; i < C * 24; i += K1_THREADS) {
                int k = i / 24, cq = (i % 24) * 4;
                float4 w = *(const float4*)&W[k * C + cq];
                WST[(cq + 0) * 100 + k] = w.x;
                WST[(cq + 1) * 100 + k] = w.y;
                WST[(cq + 2) * 100 + k] = w.z;
                WST[(cq + 3) * 100 + k] = w.w;
            }
            __syncthreads();

            u64 acc[8][3];
            #pragma unroll
            for (int pp = 0; pp < 8; pp++)
                acc[pp][0] = acc[pp][1] = acc[pp][2] = 0ull;

            #pragma unroll 2
            for (int k4 = 0; k4 < C; k4 += 4) {
                ulonglong2 b0 = *(const ulonglong2*)&WST[tx * 100 + k4];
                ulonglong2 b1 = *(const ulonglong2*)&WST[(tx + 32) * 100 + k4];
                ulonglong2 b2 = *(const ulonglong2*)&WST[(tx + 64) * 100 + k4];
                #pragma unroll
                for (int pp = 0; pp < 8; pp++) {
                    ulonglong2 a = *(const ulonglong2*)&featS[(ty * 8 + pp) * 100 + k4];
                    acc[pp][0] = fma2(a.x, b0.x, acc[pp][0]);
                    acc[pp][0] = fma2(a.y, b0.y, acc[pp][0]);
                    acc[pp][1] = fma2(a.x, b1.x, acc[pp][1]);
                    acc[pp][1] = fma2(a.y, b1.y, acc[pp][1]);
                    acc[pp][2] = fma2(a.x, b2.x, acc[pp][2]);
                    acc[pp][2] = fma2(a.y, b2.y, acc[pp][2]);
                }
            }

            if (m < 2) {
                const float* bb_ = (m == 0) ? bq : bk;
                const float* gg_ = (m == 0) ? gq : gk;
                const float* bt_ = (m == 0) ? betaq : betak;
                float bb[3], sc[3], bt[3];
                #pragma unroll
                for (int cc = 0; cc < 3; cc++) {
                    int ch = tx + 32 * cc;
                    bb[cc] = bb_[ch];
                    sc[cc] = gg_[ch] * RS;
                    bt[cc] = bt_[ch];
                }
                #pragma unroll
                for (int pp = 0; pp < 8; pp++) {
                    int p = ty * 8 + pp;
                    #pragma unroll
                    for (int cc = 0; cc < 3; cc++) {
                        float r = hsum2(acc[pp][cc]);
                        float v = fmaf(r + bb[cc], sc[cc], bt[cc]);
                        tmpS[p * 100 + tx + 32 * cc] = fmaxf(v, 0.f);
                    }
                }
                __syncthreads();
                float* dst = (m == 0) ? d_qW : d_kW;
                for (int t = tid; t < K1_TILE * G; t += K1_THREADS) {
                    int p = t / G, g = t % G;
                    int n = n0 + p;
                    if (n < NPTS) {
                        u64 s2 = 0ull;
                        #pragma unroll
                        for (int c4 = 0; c4 < C; c4 += 4) {
                            ulonglong2 hv = *(const ulonglong2*)&tmpS[p * 100 + c4];
                            ulonglong2 wv = *(const ulonglong2*)&Ww1T[g * 100 + c4];
                            s2 = fma2(hv.x, wv.x, s2);
                            s2 = fma2(hv.y, wv.y, s2);
                        }
                        dst[(size_t)n * G + g] = hsum2(s2);
                    }
                }
            } else {
                float bb[3];
                #pragma unroll
                for (int cc = 0; cc < 3; cc++) bb[cc] = bv[tx + 32 * cc];
                #pragma unroll
                for (int pp = 0; pp < 8; pp++) {
                    int p = ty * 8 + pp;
                    #pragma unroll
                    for (int cc = 0; cc < 3; cc++)
                        tmpS[p * 100 + tx + 32 * cc] = hsum2(acc[pp][cc]) + bb[cc];
                }
                __syncthreads();
                for (int i = tid; i < K1_TILE * 24; i += K1_THREADS) {
                    int p = i / 24, cq = (i % 24) * 4;
                    int n = n0 + p;
                    if (n < NPTS)
                        *(float4*)&d_v[(size_t)n * C + cq] = *(const float4*)&tmpS[p * 100 + cq];
                }
            }
        }
        __syncthreads();
    }
}

// ---------------- k2: warp-pod attention (1 warp = 1 point, no barriers) ------
#define PTS 6                       // pods (warps) per block
#define K2_THREADS (PTS * 32)       // 192
#define K2_GRID 304
#define K2_PODS (K2_GRID * PTS)     // 1824
#define POD_F 2512
// layout (floats): Wp2T 9600 | MTs 600 | cst 68 | pods
// pod: hs 0..1600 | Hs 1600..2200 | us 2200..2296 | ws 2296..2424 |
//      pos 2424..2488 | wsum 2488..2496 | js 2496..2512
#define K2_SMEM_F (C*100 + G*100 + 68 + PTS*POD_F)   // 25340 fl = 101.4KB
#define K2_SMEM (K2_SMEM_F * 4)

__global__ __launch_bounds__(K2_THREADS, 2)
void k2_attn(const float* __restrict__ coord,
             const int*   __restrict__ refidx,
             const float* __restrict__ Wp1, const float* __restrict__ bp1,
             const float* __restrict__ gp,  const float* __restrict__ betap,
             const float* __restrict__ bp2,
             const float* __restrict__ bw1, const float* __restrict__ gw,
             const float* __restrict__ betaw,
             const float* __restrict__ Ww2, const float* __restrict__ bw2,
             float* __restrict__ out)
{
    extern __shared__ float sh[];
    float* Wp2T = sh;                  // [co][ci] stride 100
    float* MTs  = sh + C * 100;        // [g][cc] stride 100
    float* cst  = MTs + G * 100;       // Ww2(36) bw2(6) bw1(6) gw(6) betaw(6) bM(6)
    float* podb = cst + 68;

    const int tid = threadIdx.x;
    const int pod = tid >> 5;          // warp id = pod
    const int l   = tid & 31;          // lane

    float* P    = podb + pod * POD_F;
    float* hs   = P;                   // [16][100]
    float* Hs   = P + 1600;            // [6][100]
    float* us   = P + 2200;            // [16][6]
    float* ws   = P + 2296;            // [16][8]
    float* pos  = P + 2424;            // [16][4]
    float* wsum = P + 2488;            // [8]
    int*   js_  = (int*)(P + 2496);    // [16]

    const float RS = rsqrtf(1.0f + 1e-5f);

    // ---- one-time block staging ----
    for (int i = tid; i < C * 24; i += K2_THREADS) {
        int co = i / 24, ciq = (i % 24) * 4;
        *(float4*)&Wp2T[co * 100 + ciq] = *(const float4*)&d_Wp2T[co * C + ciq];
    }
    for (int i = tid; i < G * C; i += K2_THREADS)
        MTs[(i / C) * 100 + (i % C)] = d_MT[i];
    if      (tid < 36) cst[tid] = Ww2[tid];
    else if (tid < 42) cst[tid] = bw2[tid - 36];
    else if (tid < 48) cst[tid] = bw1[tid - 42];
    else if (tid < 54) cst[tid] = gw[tid - 48];
    else if (tid < 60) cst[tid] = betaw[tid - 54];
    else if (tid < 66) cst[tid] = d_bM[tid - 60];

    // per-lane channel params (c0=l, c1=l+32, c2=l+64)
    const int c0 = l, c1 = l + 32, c2 = l + 64;
    float w10[3], w11[3], w12[3], b1c[3], spc[3], btc[3], bp2v[3];
    #pragma unroll
    for (int p = 0; p < 3; p++) {
        int ch = l + 32 * p;
        w10[p] = __ldg(&Wp1[ch]);
        w11[p] = __ldg(&Wp1[C + ch]);
        w12[p] = __ldg(&Wp1[2 * C + ch]);
        b1c[p] = __ldg(&bp1[ch]);
        spc[p] = __ldg(&gp[ch]) * RS;
        btc[p] = __ldg(&betap[ch]);
        bp2v[p] = __ldg(&bp2[ch]);
    }
    const bool hi = (l >= 16);
    const int gc0 = hi ? 1 : 0, gc1 = hi ? 3 : 2, gc2 = hi ? 5 : 4;
    __syncthreads();

    for (int pt = blockIdx.x * PTS + pod; pt < NPTS; pt += K2_PODS) {
        const size_t n = (size_t)pt;

        // W: indices + relative positions (lanes 0-15)
        if (l < 16) {
            int j = __ldg(&refidx[n * S + l]);
            js_[l] = j;
            float cx = __ldg(&coord[n * 3 + 0]);
            float cy = __ldg(&coord[n * 3 + 1]);
            float cz = __ldg(&coord[n * 3 + 2]);
            pos[l * 4 + 0] = __ldg(&coord[(size_t)j * 3 + 0]) - cx;
            pos[l * 4 + 1] = __ldg(&coord[(size_t)j * 3 + 1]) - cy;
            pos[l * 4 + 2] = __ldg(&coord[(size_t)j * 3 + 2]) - cz;
        }
        __syncwarp();

        // P3: h[s][c] for this lane's 3 channels
        #pragma unroll
        for (int s = 0; s < 16; s++) {
            float4 pp = *(const float4*)&pos[s * 4];   // broadcast (w unused)
            #pragma unroll
            for (int p = 0; p < 3; p++) {
                float hv = fmaf(pp.x, w10[p], fmaf(pp.y, w11[p], fmaf(pp.z, w12[p], b1c[p])));
                hv = fmaxf(fmaf(hv, spc[p], btc[p]), 0.0f);
                hs[s * 100 + l + 32 * p] = hv;
            }
        }
        __syncwarp();

        // P4: u for 3 (s,g) pairs per lane
        #pragma unroll
        for (int p = 0; p < 3; p++) {
            int idx = l + 32 * p;
            int s = idx / 6, g = idx % 6;
            u64 a0 = 0ull, a1 = 0ull;
            #pragma unroll
            for (int c8 = 0; c8 < C; c8 += 8) {
                ulonglong2 h0 = *(const ulonglong2*)&hs[s * 100 + c8];
                ulonglong2 h1 = *(const ulonglong2*)&hs[s * 100 + c8 + 4];
                ulonglong2 m0 = *(const ulonglong2*)&MTs[g * 100 + c8];
                ulonglong2 m1 = *(const ulonglong2*)&MTs[g * 100 + c8 + 4];
                a0 = fma2(h0.x, m0.x, a0);
                a1 = fma2(h0.y, m0.y, a1);
                a0 = fma2(h1.x, m1.x, a0);
                a1 = fma2(h1.y, m1.y, a1);
            }
            float dot = hsum2(a0) + hsum2(a1);
            float kq = __ldg(&d_kW[(size_t)js_[s] * G + g]) - __ldg(&d_qW[n * G + g]);
            float tt = kq + dot + cst[60 + g] + cst[42 + g];
            us[idx] = fmaxf(fmaf(tt, cst[48 + g] * RS, cst[54 + g]), 0.0f);
        }
        __syncwarp();

        // P5+P6 fused: logits + softmax + mask (lanes 0-23: 4 s-chunks x 6 g)
        if (l < 24) {
            const int q = l / 6, g2 = l % 6;
            float lg[4];
            #pragma unroll
            for (int i = 0; i < 4; i++) {
                int s = q * 4 + i;
                float lv = cst[36 + g2];
                #pragma unroll
                for (int g = 0; g < 6; g++)
                    lv = fmaf(us[s * 6 + g], cst[g * 6 + g2], lv);
                lg[i] = lv;
            }
            float lm = fmaxf(fmaxf(lg[0], lg[1]), fmaxf(lg[2], lg[3]));
            float m1 = fmaxf(lm, __shfl_down_sync(0x00FFFFFF, lm, 12));
            float m  = fmaxf(m1, __shfl_down_sync(0x00FFFFFF, m1, 6));
            m = __shfl_sync(0x00FFFFFF, m, g2);
            float e[4];
            float sm = 0.f;
            #pragma unroll
            for (int i = 0; i < 4; i++) { e[i] = __expf(lg[i] - m); sm += e[i]; }
            float sm1 = sm + __shfl_down_sync(0x00FFFFFF, sm, 12);
            float smt = sm1 + __shfl_down_sync(0x00FFFFFF, sm1, 6);
            float inv = 1.0f / __shfl_sync(0x00FFFFFF, smt, g2);
            float accw = 0.f;
            #pragma unroll
            for (int i = 0; i < 4; i++) {
                int s = q * 4 + i;
                int jp1 = js_[s] + 1;
                float msk = (float)((jp1 > 0) - (jp1 < 0));
                float w = e[i] * inv * msk;
                ws[s * 8 + g2] = w;
                accw += w;
            }
            float a1r = accw + __shfl_down_sync(0x00FFFFFF, accw, 12);
            float at  = a1r + __shfl_down_sync(0x00FFFFFF, a1r, 6);
            if (l < 6) wsum[l] = at;
        }
        __syncwarp();

        // P7: H[g][c] accumulation (f32x2) + vsum with interleaved d_v gather
        u64 HA[3] = {0,0,0}, HB[3] = {0,0,0}, HC[3] = {0,0,0};
        float vs0 = 0.f, vs1 = 0.f, vs2 = 0.f;
        #pragma unroll
        for (int s = 0; s < 16; s++) {
            ulonglong2 w03 = *(const ulonglong2*)&ws[s * 8];   // (g0g1, g2g3)
            u64 w45 = *(const u64*)&ws[s * 8 + 4];             // (g4g5)
            float h0 = hs[s * 100 + c0];
            float h1 = hs[s * 100 + c1];
            float h2 = hs[s * 100 + c2];
            u64 h0d = dup2(h0), h1d = dup2(h1), h2d = dup2(h2);
            HA[0] = fma2(h0d, w03.x, HA[0]);
            HA[1] = fma2(h0d, w03.y, HA[1]);
            HA[2] = fma2(h0d, w45,   HA[2]);
            HB[0] = fma2(h1d, w03.x, HB[0]);
            HB[1] = fma2(h1d, w03.y, HB[1]);
            HB[2] = fma2(h1d, w45,   HB[2]);
            HC[0] = fma2(h2d, w03.x, HC[0]);
            HC[1] = fma2(h2d, w03.y, HC[1]);
            HC[2] = fma2(h2d, w45,   HC[2]);
            float wg0 = hi ? hi2(w03.x) : lo2(w03.x);
            float wg1 = hi ? hi2(w03.y) : lo2(w03.y);
            float wg2 = hi ? hi2(w45)   : lo2(w45);
            int j = js_[s];
            vs0 = fmaf(wg0, __ldg(&d_v[(size_t)j * C + c0]), vs0);
            vs1 = fmaf(wg1, __ldg(&d_v[(size_t)j * C + c1]), vs1);
            vs2 = fmaf(wg2, __ldg(&d_v[(size_t)j * C + c2]), vs2);
        }
        // store H (6 g-rows x this lane's 3 channels)
        Hs[0 * 100 + c0] = lo2(HA[0]);  Hs[1 * 100 + c0] = hi2(HA[0]);
        Hs[2 * 100 + c0] = lo2(HA[1]);  Hs[3 * 100 + c0] = hi2(HA[1]);
        Hs[4 * 100 + c0] = lo2(HA[2]);  Hs[5 * 100 + c0] = hi2(HA[2]);
        Hs[0 * 100 + c1] = lo2(HB[0]);  Hs[1 * 100 + c1] = hi2(HB[0]);
        Hs[2 * 100 + c1] = lo2(HB[1]);  Hs[3 * 100 + c1] = hi2(HB[1]);
        Hs[4 * 100 + c1] = lo2(HB[2]);  Hs[5 * 100 + c1] = hi2(HB[2]);
        Hs[0 * 100 + c2] = lo2(HC[0]);  Hs[1 * 100 + c2] = hi2(HC[0]);
        Hs[2 * 100 + c2] = lo2(HC[1]);  Hs[3 * 100 + c2] = hi2(HC[1]);
        Hs[4 * 100 + c2] = lo2(HC[2]);  Hs[5 * 100 + c2] = hi2(HC[2]);
        __syncwarp();

        // P8: out[c] = vsum + bp2[c]*wsum[gc] + H[gc] . Wp2[:,c]
        float vsv[3] = {vs0, vs1, vs2};
        int   gcv[3] = {gc0, gc1, gc2};
        #pragma unroll
        for (int p = 0; p < 3; p++) {
            int cc_ = l + 32 * p;
            int gcp = gcv[p];
            u64 a0 = 0ull, a1 = 0ull;
            #pragma unroll
            for (int c8 = 0; c8 < C; c8 += 8) {
                ulonglong2 hh0 = *(const ulonglong2*)&Hs[gcp * 100 + c8];
                ulonglong2 hh1 = *(const ulonglong2*)&Hs[gcp * 100 + c8 + 4];
                ulonglong2 wv0 = *(const ulonglong2*)&Wp2T[cc_ * 100 + c8];
                ulonglong2 wv1 = *(const ulonglong2*)&Wp2T[cc_ * 100 + c8 + 4];
                a0 = fma2(hh0.x, wv0.x, a0);
                a1 = fma2(hh0.y, wv0.y, a1);
                a0 = fma2(hh1.x, wv1.x, a0);
                a1 = fma2(hh1.y, wv1.y, a1);
            }
            out[n * C + cc_] = fmaf(bp2v[p], wsum[gcp], vsv[p]) + (hsum2(a0) + hsum2(a1));
        }
        __syncwarp();   // protect js/pos/ws/Hs/us before next tile's writes
    }
}

// ---------------- host launcher ---------------------------------------------
extern "C" void kernel_launch(void* const* d_in, const int* in_sizes, int n_in,
                              void* d_out, int out_size)
{
    bool dict = (in_sizes[2] == NPTS * S);

    const float* feat  = (const float*)d_in[0];
    const float* coord = (const float*)d_in[1];
    const int*   ref   = (const int*)d_in[dict ? 2 : 24];
    int wb = dict ? 3 : 2;
    const float* Wq    = (const float*)d_in[wb + 0];
    const float* bq    = (const float*)d_in[wb + 1];
    const float* gq    = (const float*)d_in[wb + 2];
    const float* betaq = (const float*)d_in[wb + 3];
    const float* Wk    = (const float*)d_in[wb + 4];
    const float* bk    = (const float*)d_in[wb + 5];
    const float* gk    = (const float*)d_in[wb + 6];
    const float* betak = (const float*)d_in[wb + 7];
    const float* Wv    = (const float*)d_in[wb + 8];
    const float* bv    = (const float*)d_in[wb + 9];
    const float* Wp1   = (const float*)d_in[wb + 10];
    const float* bp1   = (const float*)d_in[wb + 11];
    const float* gp    = (const float*)d_in[wb + 12];
    const float* betap = (const float*)d_in[wb + 13];
    const float* Wp2   = (const float*)d_in[wb + 14];
    const float* bp2   = (const float*)d_in[wb + 15];
    const float* Ww1   = (const float*)d_in[wb + 16];
    const float* bw1   = (const float*)d_in[wb + 17];
    const float* gw    = (const float*)d_in[wb + 18];
    const float* betaw = (const float*)d_in[wb + 19];
    const float* Ww2   = (const float*)d_in[wb + 20];
    const float* bw2   = (const float*)d_in[wb + 21];
    float* out = (float*)d_out;

    cudaFuncSetAttribute(k1_qkv,  cudaFuncAttributeMaxDynamicSharedMemorySize, K1_SMEM);
    cudaFuncSetAttribute(k2_attn, cudaFuncAttributeMaxDynamicSharedMemorySize, K2_SMEM);

    k1_qkv<<<K1_GRID, K1_THREADS, K1_SMEM>>>(
        feat, Wq, bq, gq, betaq, Wk, bk, gk, betak, Wv, bv, Ww1, Wp2, bp2);
    k2_attn<<<K2_GRID, K2_THREADS, K2_SMEM>>>(
        coord, ref, Wp1, bp1, gp, betap, bp2, bw1, gw, betaw, Ww2, bw2, out);
}

// round 11
// speedup vs baseline: 1.6341x; 1.2284x over previous
#include <cuda_runtime.h>
#include <cuda_fp16.h>
#include <cstddef>

#define NPTS 50000
#define C    96
#define G    6
#define S    16

typedef unsigned long long u64;

// packed fp32x2 helpers -------------------------------------------------------
__device__ __forceinline__ u64 fma2(u64 a, u64 b, u64 c) {
    u64 d;
    asm("fma.rn.f32x2 %0, %1, %2, %3;" : "=l"(d) : "l"(a), "l"(b), "l"(c));
    return d;
}
__device__ __forceinline__ float lo2(u64 v) { return __uint_as_float((unsigned)v); }
__device__ __forceinline__ float hi2(u64 v) { return __uint_as_float((unsigned)(v >> 32)); }
__device__ __forceinline__ float hsum2(u64 v) { return lo2(v) + hi2(v); }
__device__ __forceinline__ u64 dup2(float x) {
    u64 r;
    asm("mov.b64 %0, {%1, %1};" : "=l"(r) : "r"(__float_as_uint(x)));
    return r;
}
__device__ __forceinline__ __half2 h2u(unsigned u) { return *reinterpret_cast<__half2*>(&u); }

// ---------------- scratch (static device globals) ----------------------------
__device__ float d_v   [NPTS * C];
__device__ float d_qW  [NPTS * G];
__device__ float d_kW  [NPTS * G];
__device__ float d_MT  [G * C];      // [g][cc] = (Wp2 @ Ww1)[cc][g]
__device__ float d_bM  [G];          // bp2 @ Ww1
__device__ float d_Wp2T[C * C];      // [co][ci]

// ---------------- k1: persistent QKV projections + qW/kW (unchanged) ---------
#define K1_TILE 64
#define K1_THREADS 256
#define K1_GRID 304
#define K1_TILES ((NPTS + K1_TILE - 1) / K1_TILE)
#define K1_SMEM_F (K1_TILE*100 + C*100 + K1_TILE*100 + G*100)
#define K1_SMEM (K1_SMEM_F * 4)

__global__ __launch_bounds__(K1_THREADS, 2)
void k1_qkv(const float* __restrict__ feat,
            const float* __restrict__ Wq, const float* __restrict__ bq,
            const float* __restrict__ gq, const float* __restrict__ betaq,
            const float* __restrict__ Wk, const float* __restrict__ bk,
            const float* __restrict__ gk, const float* __restrict__ betak,
            const float* __restrict__ Wv, const float* __restrict__ bv,
            const float* __restrict__ Ww1,
            const float* __restrict__ Wp2, const float* __restrict__ bp2)
{
    const int tid = threadIdx.x;

    if (blockIdx.x == 0) {   // precompute for k2
        for (int i = tid; i < C * C; i += K1_THREADS) {
            int co = i / C, ci = i % C;
            d_Wp2T[i] = __ldg(&Wp2[ci * C + co]);
        }
        for (int i = tid; i < G * C; i += K1_THREADS) {
            int g = i / C, cc = i % C;
            float s = 0.f;
            #pragma unroll 4
            for (int c2 = 0; c2 < C; c2++)
                s = fmaf(__ldg(&Wp2[cc * C + c2]), __ldg(&Ww1[c2 * G + g]), s);
            d_MT[i] = s;
        }
        if (tid < G) {
            float s = 0.f;
            for (int c2 = 0; c2 < C; c2++)
                s = fmaf(__ldg(&bp2[c2]), __ldg(&Ww1[c2 * G + tid]), s);
            d_bM[tid] = s;
        }
    }

    extern __shared__ float sh[];
    float* featS = sh;                        // [p][k] stride 100
    float* WST   = sh + K1_TILE * 100;        // [c][k] stride 100
    float* tmpS  = WST + C * 100;             // [p][c] stride 100
    float* Ww1T  = tmpS + K1_TILE * 100;      // [g][c] stride 100

    const float RS = rsqrtf(1.0f + 1e-5f);
    const int tx = tid & 31, ty = tid >> 5;

    for (int i = tid; i < C * G; i += K1_THREADS) {
        int c2 = i / G, g = i % G;
        Ww1T[g * 100 + c2] = Ww1[i];
    }

    for (int tile = blockIdx.x; tile < K1_TILES; tile += K1_GRID) {
        const int n0 = tile * K1_TILE;

        for (int i = tid; i < K1_TILE * 24; i += K1_THREADS) {
            int p = i / 24, kq = (i % 24) * 4;
            int n = n0 + p;
            float4 vv = (n < NPTS) ? *(const float4*)&feat[(size_t)n * C + kq]
                                   : make_float4(0.f, 0.f, 0.f, 0.f);
            *(float4*)&featS[p * 100 + kq] = vv;
        }

        for (int m = 0; m < 3; m++) {
            __syncthreads();
            const float* W = (m == 0) ? Wq : (m == 1) ? Wk : Wv;
            for (int i = tid; i < C * 24; i += K1_THREADS) {
                int k = i / 24, cq = (i % 24) * 4;
                float4 w = *(const float4*)&W[k * C + cq];
                WST[(cq + 0) * 100 + k] = w.x;
                WST[(cq + 1) * 100 + k] = w.y;
                WST[(cq + 2) * 100 + k] = w.z;
                WST[(cq + 3) * 100 + k] = w.w;
            }
            __syncthreads();

            u64 acc[8][3];
            #pragma unroll
            for (int pp = 0; pp < 8; pp++)
                acc[pp][0] = acc[pp][1] = acc[pp][2] = 0ull;

            #pragma unroll 2
            for (int k4 = 0; k4 < C; k4 += 4) {
                ulonglong2 b0 = *(const ulonglong2*)&WST[tx * 100 + k4];
                ulonglong2 b1 = *(const ulonglong2*)&WST[(tx + 32) * 100 + k4];
                ulonglong2 b2 = *(const ulonglong2*)&WST[(tx + 64) * 100 + k4];
                #pragma unroll
                for (int pp = 0; pp < 8; pp++) {
                    ulonglong2 a = *(const ulonglong2*)&featS[(ty * 8 + pp) * 100 + k4];
                    acc[pp][0] = fma2(a.x, b0.x, acc[pp][0]);
                    acc[pp][0] = fma2(a.y, b0.y, acc[pp][0]);
                    acc[pp][1] = fma2(a.x, b1.x, acc[pp][1]);
                    acc[pp][1] = fma2(a.y, b1.y, acc[pp][1]);
                    acc[pp][2] = fma2(a.x, b2.x, acc[pp][2]);
                    acc[pp][2] = fma2(a.y, b2.y, acc[pp][2]);
                }
            }

            if (m < 2) {
                const float* bb_ = (m == 0) ? bq : bk;
                const float* gg_ = (m == 0) ? gq : gk;
                const float* bt_ = (m == 0) ? betaq : betak;
                float bb[3], sc[3], bt[3];
                #pragma unroll
                for (int cc = 0; cc < 3; cc++) {
                    int ch = tx + 32 * cc;
                    bb[cc] = bb_[ch];
                    sc[cc] = gg_[ch] * RS;
                    bt[cc] = bt_[ch];
                }
                #pragma unroll
                for (int pp = 0; pp < 8; pp++) {
                    int p = ty * 8 + pp;
                    #pragma unroll
                    for (int cc = 0; cc < 3; cc++) {
                        float r = hsum2(acc[pp][cc]);
                        float v = fmaf(r + bb[cc], sc[cc], bt[cc]);
                        tmpS[p * 100 + tx + 32 * cc] = fmaxf(v, 0.f);
                    }
                }
                __syncthreads();
                float* dst = (m == 0) ? d_qW : d_kW;
                for (int t = tid; t < K1_TILE * G; t += K1_THREADS) {
                    int p = t / G, g = t % G;
                    int n = n0 + p;
                    if (n < NPTS) {
                        u64 s2 = 0ull;
                        #pragma unroll
                        for (int c4 = 0; c4 < C; c4 += 4) {
                            ulonglong2 hv = *(const ulonglong2*)&tmpS[p * 100 + c4];
                            ulonglong2 wv = *(const ulonglong2*)&Ww1T[g * 100 + c4];
                            s2 = fma2(hv.x, wv.x, s2);
                            s2 = fma2(hv.y, wv.y, s2);
                        }
                        dst[(size_t)n * G + g] = hsum2(s2);
                    }
                }
            } else {
                float bb[3];
                #pragma unroll
                for (int cc = 0; cc < 3; cc++) bb[cc] = bv[tx + 32 * cc];
                #pragma unroll
                for (int pp = 0; pp < 8; pp++) {
                    int p = ty * 8 + pp;
                    #pragma unroll
                    for (int cc = 0; cc < 3; cc++)
                        tmpS[p * 100 + tx + 32 * cc] = hsum2(acc[pp][cc]) + bb[cc];
                }
                __syncthreads();
                for (int i = tid; i < K1_TILE * 24; i += K1_THREADS) {
                    int p = i / 24, cq = (i % 24) * 4;
                    int n = n0 + p;
                    if (n < NPTS)
                        *(float4*)&d_v[(size_t)n * C + cq] = *(const float4*)&tmpS[p * 100 + cq];
                }
            }
        }
        __syncthreads();
    }
}

// ---------------- k2: warp-pod attention + fp16 smem for big dots ------------
#define PTS 6                       // pods (warps) per block
#define K2_THREADS (PTS * 32)       // 192
#define K2_GRID 304
#define K2_PODS (K2_GRID * PTS)     // 1824
// half stride for 96-wide rows: 104 halves = 208B (16B aligned)
#define HST 104
// block byte layout
#define OFF_WP2T 0                          // 96*104*2 = 19968 B
#define OFF_MT   19968                      // 6*104*2 = 1248 B
#define OFF_CST  21216                      // 72 floats = 288 B
#define OFF_POD  21504
// pod byte layout: hs_h 0..3328 | Hs_h 3328..4576 | ws 4576..5088 |
//   us 5088..5472 | pos 5472..5728 | wsum 5728..5760 | js 5760..5824 | pad
#define POD_B 5888
#define K2_SMEM (OFF_POD + PTS * POD_B)     // 56832 B

__global__ __launch_bounds__(K2_THREADS, 2)
void k2_attn(const float* __restrict__ coord,
             const int*   __restrict__ refidx,
             const float* __restrict__ Wp1, const float* __restrict__ bp1,
             const float* __restrict__ gp,  const float* __restrict__ betap,
             const float* __restrict__ bp2,
             const float* __restrict__ bw1, const float* __restrict__ gw,
             const float* __restrict__ betaw,
             const float* __restrict__ Ww2, const float* __restrict__ bw2,
             float* __restrict__ out)
{
    extern __shared__ __align__(16) unsigned char smraw[];
    __half* Wp2Th = (__half*)(smraw + OFF_WP2T);   // [co][ci] stride 104
    __half* MTh   = (__half*)(smraw + OFF_MT);     // [g][cc] stride 104
    float*  cst   = (float*)(smraw + OFF_CST);

    const int tid = threadIdx.x;
    const int pod = tid >> 5;
    const int l   = tid & 31;

    unsigned char* P = smraw + OFF_POD + pod * POD_B;
    __half* hs_h = (__half*)(P);            // [16][104]
    __half* Hs_h = (__half*)(P + 3328);     // [6][104]
    float*  ws   = (float*)(P + 4576);      // [16][8]
    float*  us   = (float*)(P + 5088);      // [16][6]
    float*  pos  = (float*)(P + 5472);      // [16][4]
    float*  wsum = (float*)(P + 5728);      // [8]
    int*    js_  = (int*)(P + 5760);        // [16]

    const float RS = rsqrtf(1.0f + 1e-5f);

    // ---- one-time block staging ----
    for (int i = tid; i < C * 24; i += K2_THREADS) {
        int co = i / 24, ciq = (i % 24) * 4;
        float4 v = *(const float4*)&d_Wp2T[co * C + ciq];
        *(__half2*)&Wp2Th[co * HST + ciq]     = __floats2half2_rn(v.x, v.y);
        *(__half2*)&Wp2Th[co * HST + ciq + 2] = __floats2half2_rn(v.z, v.w);
    }
    for (int i = tid; i < G * C; i += K2_THREADS)
        MTh[(i / C) * HST + (i % C)] = __float2half(d_MT[i]);
    if      (tid < 36) cst[tid] = Ww2[tid];
    else if (tid < 42) cst[tid] = bw2[tid - 36];
    else if (tid < 48) cst[tid] = bw1[tid - 42];
    else if (tid < 54) cst[tid] = gw[tid - 48];
    else if (tid < 60) cst[tid] = betaw[tid - 54];
    else if (tid < 66) cst[tid] = d_bM[tid - 60];

    // per-lane channel params (c0=l, c1=l+32, c2=l+64)
    const int c0 = l, c1 = l + 32, c2 = l + 64;
    float w10[3], w11[3], w12[3], b1c[3], spc[3], btc[3], bp2v[3];
    #pragma unroll
    for (int p = 0; p < 3; p++) {
        int ch = l + 32 * p;
        w10[p] = __ldg(&Wp1[ch]);
        w11[p] = __ldg(&Wp1[C + ch]);
        w12[p] = __ldg(&Wp1[2 * C + ch]);
        b1c[p] = __ldg(&bp1[ch]);
        spc[p] = __ldg(&gp[ch]) * RS;
        btc[p] = __ldg(&betap[ch]);
        bp2v[p] = __ldg(&bp2[ch]);
    }
    const bool hi = (l >= 16);
    const int gc0 = hi ? 1 : 0, gc1 = hi ? 3 : 2, gc2 = hi ? 5 : 4;
    __syncthreads();

    for (int pt = blockIdx.x * PTS + pod; pt < NPTS; pt += K2_PODS) {
        const size_t n = (size_t)pt;

        // W: indices + relative positions (lanes 0-15)
        if (l < 16) {
            int j = __ldg(&refidx[n * S + l]);
            js_[l] = j;
            float cx = __ldg(&coord[n * 3 + 0]);
            float cy = __ldg(&coord[n * 3 + 1]);
            float cz = __ldg(&coord[n * 3 + 2]);
            pos[l * 4 + 0] = __ldg(&coord[(size_t)j * 3 + 0]) - cx;
            pos[l * 4 + 1] = __ldg(&coord[(size_t)j * 3 + 1]) - cy;
            pos[l * 4 + 2] = __ldg(&coord[(size_t)j * 3 + 2]) - cz;
        }
        __syncwarp();

        // P3: h[s][c] for this lane's 3 channels (fp32 math, fp16 store)
        #pragma unroll
        for (int s = 0; s < 16; s++) {
            float4 pp = *(const float4*)&pos[s * 4];
            #pragma unroll
            for (int p = 0; p < 3; p++) {
                float hv = fmaf(pp.x, w10[p], fmaf(pp.y, w11[p], fmaf(pp.z, w12[p], b1c[p])));
                hv = fmaxf(fmaf(hv, spc[p], btc[p]), 0.0f);
                hs_h[s * HST + l + 32 * p] = __float2half(hv);
            }
        }
        __syncwarp();

        // P4: u for 3 (s,g) pairs per lane  (fp16 dot, half2 x2 accums)
        #pragma unroll
        for (int p = 0; p < 3; p++) {
            int idx = l + 32 * p;
            int s = idx / 6, g = idx % 6;
            const uint4* hp = (const uint4*)(hs_h + s * HST);
            const uint4* mp = (const uint4*)(MTh + g * HST);
            __half2 a0 = __float2half2_rn(0.f), a1 = a0;
            #pragma unroll
            for (int i = 0; i < 12; i++) {
                uint4 hu = hp[i], mu = mp[i];
                a0 = __hfma2(h2u(hu.x), h2u(mu.x), a0);
                a1 = __hfma2(h2u(hu.y), h2u(mu.y), a1);
                a0 = __hfma2(h2u(hu.z), h2u(mu.z), a0);
                a1 = __hfma2(h2u(hu.w), h2u(mu.w), a1);
            }
            float2 f0 = __half22float2(a0), f1 = __half22float2(a1);
            float dot = (f0.x + f0.y) + (f1.x + f1.y);
            float kq = __ldg(&d_kW[(size_t)js_[s] * G + g]) - __ldg(&d_qW[n * G + g]);
            float tt = kq + dot + cst[60 + g] + cst[42 + g];
            us[idx] = fmaxf(fmaf(tt, cst[48 + g] * RS, cst[54 + g]), 0.0f);
        }
        __syncwarp();

        // P5+P6 fused: logits + softmax + mask (lanes 0-23: 4 s-chunks x 6 g)
        if (l < 24) {
            const int q = l / 6, g2 = l % 6;
            float lg[4];
            #pragma unroll
            for (int i = 0; i < 4; i++) {
                int s = q * 4 + i;
                float lv = cst[36 + g2];
                #pragma unroll
                for (int g = 0; g < 6; g++)
                    lv = fmaf(us[s * 6 + g], cst[g * 6 + g2], lv);
                lg[i] = lv;
            }
            float lm = fmaxf(fmaxf(lg[0], lg[1]), fmaxf(lg[2], lg[3]));
            float m1 = fmaxf(lm, __shfl_down_sync(0x00FFFFFF, lm, 12));
            float m  = fmaxf(m1, __shfl_down_sync(0x00FFFFFF, m1, 6));
            m = __shfl_sync(0x00FFFFFF, m, g2);
            float e[4];
            float sm = 0.f;
            #pragma unroll
            for (int i = 0; i < 4; i++) { e[i] = __expf(lg[i] - m); sm += e[i]; }
            float sm1 = sm + __shfl_down_sync(0x00FFFFFF, sm, 12);
            float smt = sm1 + __shfl_down_sync(0x00FFFFFF, sm1, 6);
            float inv = 1.0f / __shfl_sync(0x00FFFFFF, smt, g2);
            float accw = 0.f;
            #pragma unroll
            for (int i = 0; i < 4; i++) {
                int s = q * 4 + i;
                int jp1 = js_[s] + 1;
                float msk = (float)((jp1 > 0) - (jp1 < 0));
                float w = e[i] * inv * msk;
                ws[s * 8 + g2] = w;
                accw += w;
            }
            float a1r = accw + __shfl_down_sync(0x00FFFFFF, accw, 12);
            float at  = a1r + __shfl_down_sync(0x00FFFFFF, a1r, 6);
            if (l < 6) wsum[l] = at;
        }
        __syncwarp();

        // P7: H[g][c] accumulation (fp32) + vsum with interleaved d_v gather
        u64 HA[3] = {0,0,0}, HB[3] = {0,0,0}, HC[3] = {0,0,0};
        float vs0 = 0.f, vs1 = 0.f, vs2 = 0.f;
        #pragma unroll
        for (int s = 0; s < 16; s++) {
            ulonglong2 w03 = *(const ulonglong2*)&ws[s * 8];   // (g0g1, g2g3)
            u64 w45 = *(const u64*)&ws[s * 8 + 4];             // (g4g5)
            float h0 = __half2float(hs_h[s * HST + c0]);
            float h1 = __half2float(hs_h[s * HST + c1]);
            float h2 = __half2float(hs_h[s * HST + c2]);
            u64 h0d = dup2(h0), h1d = dup2(h1), h2d = dup2(h2);
            HA[0] = fma2(h0d, w03.x, HA[0]);
            HA[1] = fma2(h0d, w03.y, HA[1]);
            HA[2] = fma2(h0d, w45,   HA[2]);
            HB[0] = fma2(h1d, w03.x, HB[0]);
            HB[1] = fma2(h1d, w03.y, HB[1]);
            HB[2] = fma2(h1d, w45,   HB[2]);
            HC[0] = fma2(h2d, w03.x, HC[0]);
            HC[1] = fma2(h2d, w03.y, HC[1]);
            HC[2] = fma2(h2d, w45,   HC[2]);
            float wg0 = hi ? hi2(w03.x) : lo2(w03.x);
            float wg1 = hi ? hi2(w03.y) : lo2(w03.y);
            float wg2 = hi ? hi2(w45)   : lo2(w45);
            int j = js_[s];
            vs0 = fmaf(wg0, __ldg(&d_v[(size_t)j * C + c0]), vs0);
            vs1 = fmaf(wg1, __ldg(&d_v[(size_t)j * C + c1]), vs1);
            vs2 = fmaf(wg2, __ldg(&d_v[(size_t)j * C + c2]), vs2);
        }
        // store H rows (fp16)
        Hs_h[0 * HST + c0] = __float2half(lo2(HA[0]));
        Hs_h[1 * HST + c0] = __float2half(hi2(HA[0]));
        Hs_h[2 * HST + c0] = __float2half(lo2(HA[1]));
        Hs_h[3 * HST + c0] = __float2half(hi2(HA[1]));
        Hs_h[4 * HST + c0] = __float2half(lo2(HA[2]));
        Hs_h[5 * HST + c0] = __float2half(hi2(HA[2]));
        Hs_h[0 * HST + c1] = __float2half(lo2(HB[0]));
        Hs_h[1 * HST + c1] = __float2half(hi2(HB[0]));
        Hs_h[2 * HST + c1] = __float2half(lo2(HB[1]));
        Hs_h[3 * HST + c1] = __float2half(hi2(HB[1]));
        Hs_h[4 * HST + c1] = __float2half(lo2(HB[2]));
        Hs_h[5 * HST + c1] = __float2half(hi2(HB[2]));
        Hs_h[0 * HST + c2] = __float2half(lo2(HC[0]));
        Hs_h[1 * HST + c2] = __float2half(hi2(HC[0]));
        Hs_h[2 * HST + c2] = __float2half(lo2(HC[1]));
        Hs_h[3 * HST + c2] = __float2half(hi2(HC[1]));
        Hs_h[4 * HST + c2] = __float2half(lo2(HC[2]));
        Hs_h[5 * HST + c2] = __float2half(hi2(HC[2]));
        __syncwarp();

        // P8: out[c] = vsum + bp2[c]*wsum[gc] + H[gc] . Wp2[:,c]  (fp16 dot)
        float vsv[3] = {vs0, vs1, vs2};
        int   gcv[3] = {gc0, gc1, gc2};
        #pragma unroll
        for (int p = 0; p < 3; p++) {
            int cc_ = l + 32 * p;
            int gcp = gcv[p];
            const uint4* wp = (const uint4*)(Wp2Th + cc_ * HST);
            const uint4* hp = (const uint4*)(Hs_h + gcp * HST);
            __half2 b0 = __float2half2_rn(0.f), b1 = b0, b2 = b0, b3 = b0;
            #pragma unroll
            for (int i = 0; i < 12; i++) {
                uint4 wu = wp[i], hu = hp[i];
                b0 = __hfma2(h2u(wu.x), h2u(hu.x), b0);
                b1 = __hfma2(h2u(wu.y), h2u(hu.y), b1);
                b2 = __hfma2(h2u(wu.z), h2u(hu.z), b2);
                b3 = __hfma2(h2u(wu.w), h2u(hu.w), b3);
            }
            float2 f0 = __half22float2(b0), f1 = __half22float2(b1);
            float2 f2 = __half22float2(b2), f3 = __half22float2(b3);
            float dot = ((f0.x + f0.y) + (f1.x + f1.y)) + ((f2.x + f2.y) + (f3.x + f3.y));
            out[n * C + cc_] = fmaf(bp2v[p], wsum[gcp], vsv[p]) + dot;
        }
        __syncwarp();   // protect pod buffers before next tile's writes
    }
}

// ---------------- host launcher ---------------------------------------------
extern "C" void kernel_launch(void* const* d_in, const int* in_sizes, int n_in,
                              void* d_out, int out_size)
{
    bool dict = (in_sizes[2] == NPTS * S);

    const float* feat  = (const float*)d_in[0];
    const float* coord = (const float*)d_in[1];
    const int*   ref   = (const int*)d_in[dict ? 2 : 24];
    int wb = dict ? 3 : 2;
    const float* Wq    = (const float*)d_in[wb + 0];
    const float* bq    = (const float*)d_in[wb + 1];
    const float* gq    = (const float*)d_in[wb + 2];
    const float* betaq = (const float*)d_in[wb + 3];
    const float* Wk    = (const float*)d_in[wb + 4];
    const float* bk    = (const float*)d_in[wb + 5];
    const float* gk    = (const float*)d_in[wb + 6];
    const float* betak = (const float*)d_in[wb + 7];
    const float* Wv    = (const float*)d_in[wb + 8];
    const float* bv    = (const float*)d_in[wb + 9];
    const float* Wp1   = (const float*)d_in[wb + 10];
    const float* bp1   = (const float*)d_in[wb + 11];
    const float* gp    = (const float*)d_in[wb + 12];
    const float* betap = (const float*)d_in[wb + 13];
    const float* Wp2   = (const float*)d_in[wb + 14];
    const float* bp2   = (const float*)d_in[wb + 15];
    const float* Ww1   = (const float*)d_in[wb + 16];
    const float* bw1   = (const float*)d_in[wb + 17];
    const float* gw    = (const float*)d_in[wb + 18];
    const float* betaw = (const float*)d_in[wb + 19];
    const float* Ww2   = (const float*)d_in[wb + 20];
    const float* bw2   = (const float*)d_in[wb + 21];
    float* out = (float*)d_out;

    cudaFuncSetAttribute(k1_qkv,  cudaFuncAttributeMaxDynamicSharedMemorySize, K1_SMEM);
    cudaFuncSetAttribute(k2_attn, cudaFuncAttributeMaxDynamicSharedMemorySize, K2_SMEM);

    k1_qkv<<<K1_GRID, K1_THREADS, K1_SMEM>>>(
        feat, Wq, bq, gq, betaq, Wk, bk, gk, betak, Wv, bv, Ww1, Wp2, bp2);
    k2_attn<<<K2_GRID, K2_THREADS, K2_SMEM>>>(
        coord, ref, Wp1, bp1, gp, betap, bp2, bw1, gw, betaw, Ww2, bw2, out);
}

// round 13
// speedup vs baseline: 2.0247x; 1.2390x over previous
#include <cuda_runtime.h>
#include <cuda_fp16.h>
#include <cstddef>

#define NPTS 50000
#define C    96
#define G    6
#define S    16

typedef unsigned long long u64;

// packed fp32x2 helpers -------------------------------------------------------
__device__ __forceinline__ u64 fma2(u64 a, u64 b, u64 c) {
    u64 d;
    asm("fma.rn.f32x2 %0, %1, %2, %3;" : "=l"(d) : "l"(a), "l"(b), "l"(c));
    return d;
}
__device__ __forceinline__ float lo2(u64 v) { return __uint_as_float((unsigned)v); }
__device__ __forceinline__ float hi2(u64 v) { return __uint_as_float((unsigned)(v >> 32)); }
__device__ __forceinline__ float hsum2(u64 v) { return lo2(v) + hi2(v); }
__device__ __forceinline__ u64 dup2(float x) {
    u64 r;
    asm("mov.b64 %0, {%1, %1};" : "=l"(r) : "r"(__float_as_uint(x)));
    return r;
}
__device__ __forceinline__ __half2 h2u(unsigned u) { return *reinterpret_cast<__half2*>(&u); }
__device__ __forceinline__ float h2sum(__half2 a) {
    float2 f = __half22float2(a);
    return f.x + f.y;
}

// ---------------- scratch (static device globals) ----------------------------
__device__ float d_v   [NPTS * C];
__device__ float d_qW  [NPTS * G];
__device__ float d_kW  [NPTS * G];
__device__ float d_MT  [G * C];      // [g][cc] = (Wp2 @ Ww1)[cc][g]
__device__ float d_bM  [G];          // bp2 @ Ww1
__device__ float d_Wp2T[C * C];      // [co][ci]

// ---------------- k1: persistent QKV projections, fp16 smem GEMM -------------
#define K1_TILE 88                    // 8 warps x 11 points
#define K1_THREADS 256
#define K1_GRID 304
#define K1_TILES ((NPTS + K1_TILE - 1) / K1_TILE)   // 569 <= 2*304
#define HS1 104                       // halves per row (96 + 8 pad)
// byte offsets
#define K1_FEAT 0                                   // 88*104*2 = 18304
#define K1_WST  18304                               // 96*104*2 = 19968
#define K1_TMP  38272                               // 88*104*2 = 18304
#define K1_WW1  56576                               // 6*104*2  = 1248
#define K1_SMEM 57824

__global__ __launch_bounds__(K1_THREADS, 2)
void k1_qkv(const float* __restrict__ feat,
            const float* __restrict__ Wq, const float* __restrict__ bq,
            const float* __restrict__ gq, const float* __restrict__ betaq,
            const float* __restrict__ Wk, const float* __restrict__ bk,
            const float* __restrict__ gk, const float* __restrict__ betak,
            const float* __restrict__ Wv, const float* __restrict__ bv,
            const float* __restrict__ Ww1,
            const float* __restrict__ Wp2, const float* __restrict__ bp2)
{
    const int tid = threadIdx.x;

    // precompute for k2 on a light (1-tile) block
    if (blockIdx.x == K1_GRID - 1) {
        for (int i = tid; i < C * C; i += K1_THREADS) {
            int co = i / C, ci = i % C;
            d_Wp2T[i] = __ldg(&Wp2[ci * C + co]);
        }
        for (int i = tid; i < G * C; i += K1_THREADS) {
            int g = i / C, cc = i % C;
            float s = 0.f;
            #pragma unroll 4
            for (int c2 = 0; c2 < C; c2++)
                s = fmaf(__ldg(&Wp2[cc * C + c2]), __ldg(&Ww1[c2 * G + g]), s);
            d_MT[i] = s;
        }
        if (tid < G) {
            float s = 0.f;
            for (int c2 = 0; c2 < C; c2++)
                s = fmaf(__ldg(&bp2[c2]), __ldg(&Ww1[c2 * G + tid]), s);
            d_bM[tid] = s;
        }
    }

    extern __shared__ __align__(16) unsigned char smraw[];
    __half* featH = (__half*)(smraw + K1_FEAT);   // [p][k] stride 104
    __half* wstH  = (__half*)(smraw + K1_WST);    // [c][k] stride 104
    __half* tmpH  = (__half*)(smraw + K1_TMP);    // [p][c] stride 104
    __half* ww1H  = (__half*)(smraw + K1_WW1);    // [g][c] stride 104

    const float RS = rsqrtf(1.0f + 1e-5f);
    const int tx = tid & 31, ty = tid >> 5;   // lane = channel base, warp = point group

    for (int i = tid; i < C * G; i += K1_THREADS) {
        int c2 = i / G, g = i % G;
        ww1H[g * HS1 + c2] = __float2half(Ww1[i]);
    }

    for (int tile = blockIdx.x; tile < K1_TILES; tile += K1_GRID) {
        const int n0 = tile * K1_TILE;

        // stage feat tile (fp32 float4 -> fp16)
        for (int i = tid; i < K1_TILE * 24; i += K1_THREADS) {
            int p = i / 24, kq = (i % 24) * 4;
            int n = n0 + p;
            float4 vv = (n < NPTS) ? *(const float4*)&feat[(size_t)n * C + kq]
                                   : make_float4(0.f, 0.f, 0.f, 0.f);
            *(__half2*)&featH[p * HS1 + kq]     = __floats2half2_rn(vv.x, vv.y);
            *(__half2*)&featH[p * HS1 + kq + 2] = __floats2half2_rn(vv.z, vv.w);
        }

        for (int m = 0; m < 3; m++) {
            __syncthreads();
            const float* W = (m == 0) ? Wq : (m == 1) ? Wk : Wv;
            // stage transposed weights fp16: wstH[c][k]
            for (int i = tid; i < C * 24; i += K1_THREADS) {
                int k = i / 24, cq = (i % 24) * 4;
                float4 w = *(const float4*)&W[k * C + cq];
                wstH[(cq + 0) * HS1 + k] = __float2half(w.x);
                wstH[(cq + 1) * HS1 + k] = __float2half(w.y);
                wstH[(cq + 2) * HS1 + k] = __float2half(w.z);
                wstH[(cq + 3) * HS1 + k] = __float2half(w.w);
            }
            __syncthreads();

            // GEMM: 11 points x 3 channels per lane, hfma2, 2 chains/(p,c)
            __half2 accA[11][3], accB[11][3];
            #pragma unroll
            for (int pp = 0; pp < 11; pp++)
                #pragma unroll
                for (int cc = 0; cc < 3; cc++) {
                    accA[pp][cc] = __float2half2_rn(0.f);
                    accB[pp][cc] = __float2half2_rn(0.f);
                }

            #pragma unroll
            for (int k8 = 0; k8 < C; k8 += 8) {
                uint4 b0 = *(const uint4*)&wstH[tx * HS1 + k8];
                uint4 b1 = *(const uint4*)&wstH[(tx + 32) * HS1 + k8];
                uint4 b2 = *(const uint4*)&wstH[(tx + 64) * HS1 + k8];
                #pragma unroll
                for (int pp = 0; pp < 11; pp++) {
                    uint4 a = *(const uint4*)&featH[(ty * 11 + pp) * HS1 + k8];
                    accA[pp][0] = __hfma2(h2u(a.x), h2u(b0.x), accA[pp][0]);
                    accB[pp][0] = __hfma2(h2u(a.y), h2u(b0.y), accB[pp][0]);
                    accA[pp][0] = __hfma2(h2u(a.z), h2u(b0.z), accA[pp][0]);
                    accB[pp][0] = __hfma2(h2u(a.w), h2u(b0.w), accB[pp][0]);
                    accA[pp][1] = __hfma2(h2u(a.x), h2u(b1.x), accA[pp][1]);
                    accB[pp][1] = __hfma2(h2u(a.y), h2u(b1.y), accB[pp][1]);
                    accA[pp][1] = __hfma2(h2u(a.z), h2u(b1.z), accA[pp][1]);
                    accB[pp][1] = __hfma2(h2u(a.w), h2u(b1.w), accB[pp][1]);
                    accA[pp][2] = __hfma2(h2u(a.x), h2u(b2.x), accA[pp][2]);
                    accB[pp][2] = __hfma2(h2u(a.y), h2u(b2.y), accB[pp][2]);
                    accA[pp][2] = __hfma2(h2u(a.z), h2u(b2.z), accA[pp][2]);
                    accB[pp][2] = __hfma2(h2u(a.w), h2u(b2.w), accB[pp][2]);
                }
            }

            if (m < 2) {
                const float* bb_ = (m == 0) ? bq : bk;
                const float* gg_ = (m == 0) ? gq : gk;
                const float* bt_ = (m == 0) ? betaq : betak;
                float bb[3], sc[3], bt[3];
                #pragma unroll
                for (int cc = 0; cc < 3; cc++) {
                    int ch = tx + 32 * cc;
                    bb[cc] = bb_[ch];
                    sc[cc] = gg_[ch] * RS;
                    bt[cc] = bt_[ch];
                }
                #pragma unroll
                for (int pp = 0; pp < 11; pp++) {
                    int p = ty * 11 + pp;
                    #pragma unroll
                    for (int cc = 0; cc < 3; cc++) {
                        float r = h2sum(accA[pp][cc]) + h2sum(accB[pp][cc]);
                        float v = fmaf(r + bb[cc], sc[cc], bt[cc]);
                        tmpH[p * HS1 + tx + 32 * cc] = __float2half(fmaxf(v, 0.f));
                    }
                }
                __syncthreads();
                // qW/kW reduction (fp16 dots)
                float* dst = (m == 0) ? d_qW : d_kW;
                for (int t = tid; t < K1_TILE * G; t += K1_THREADS) {
                    int p = t / G, g = t % G;
                    int n = n0 + p;
                    if (n < NPTS) {
                        const uint4* hp = (const uint4*)(tmpH + p * HS1);
                        const uint4* wp = (const uint4*)(ww1H + g * HS1);
                        __half2 a0 = __float2half2_rn(0.f), a1 = a0;
                        #pragma unroll
                        for (int i = 0; i < 12; i++) {
                            uint4 hu = hp[i], wu = wp[i];
                            a0 = __hfma2(h2u(hu.x), h2u(wu.x), a0);
                            a1 = __hfma2(h2u(hu.y), h2u(wu.y), a1);
                            a0 = __hfma2(h2u(hu.z), h2u(wu.z), a0);
                            a1 = __hfma2(h2u(hu.w), h2u(wu.w), a1);
                        }
                        dst[(size_t)n * G + g] = h2sum(a0) + h2sum(a1);
                    }
                }
            } else {
                // v: direct coalesced stores from registers
                float bb[3];
                #pragma unroll
                for (int cc = 0; cc < 3; cc++) bb[cc] = bv[tx + 32 * cc];
                #pragma unroll
                for (int pp = 0; pp < 11; pp++) {
                    int n = n0 + ty * 11 + pp;
                    if (n < NPTS) {
                        #pragma unroll
                        for (int cc = 0; cc < 3; cc++) {
                            float r = h2sum(accA[pp][cc]) + h2sum(accB[pp][cc]);
                            d_v[(size_t)n * C + tx + 32 * cc] = r + bb[cc];
                        }
                    }
                }
            }
        }
        __syncthreads();   // tile boundary: protect featH before restage
    }
}

// ---------------- k2: warp-pod attention + fp16 smem (R11, unchanged) --------
#define PTS 6
#define K2_THREADS (PTS * 32)       // 192
#define K2_GRID 304
#define K2_PODS (K2_GRID * PTS)
#define HST 104
#define OFF_WP2T 0
#define OFF_MT   19968
#define OFF_CST  21216
#define OFF_POD  21504
#define POD_B 5888
#define K2_SMEM (OFF_POD + PTS * POD_B)     // 56832 B

__global__ __launch_bounds__(K2_THREADS, 2)
void k2_attn(const float* __restrict__ coord,
             const int*   __restrict__ refidx,
             const float* __restrict__ Wp1, const float* __restrict__ bp1,
             const float* __restrict__ gp,  const float* __restrict__ betap,
             const float* __restrict__ bp2,
             const float* __restrict__ bw1, const float* __restrict__ gw,
             const float* __restrict__ betaw,
             const float* __restrict__ Ww2, const float* __restrict__ bw2,
             float* __restrict__ out)
{
    extern __shared__ __align__(16) unsigned char smraw[];
    __half* Wp2Th = (__half*)(smraw + OFF_WP2T);
    __half* MTh   = (__half*)(smraw + OFF_MT);
    float*  cst   = (float*)(smraw + OFF_CST);

    const int tid = threadIdx.x;
    const int pod = tid >> 5;
    const int l   = tid & 31;

    unsigned char* P = smraw + OFF_POD + pod * POD_B;
    __half* hs_h = (__half*)(P);
    __half* Hs_h = (__half*)(P + 3328);
    float*  ws   = (float*)(P + 4576);
    float*  us   = (float*)(P + 5088);
    float*  pos  = (float*)(P + 5472);
    float*  wsum = (float*)(P + 5728);
    int*    js_  = (int*)(P + 5760);

    const float RS = rsqrtf(1.0f + 1e-5f);

    for (int i = tid; i < C * 24; i += K2_THREADS) {
        int co = i / 24, ciq = (i % 24) * 4;
        float4 v = *(const float4*)&d_Wp2T[co * C + ciq];
        *(__half2*)&Wp2Th[co * HST + ciq]     = __floats2half2_rn(v.x, v.y);
        *(__half2*)&Wp2Th[co * HST + ciq + 2] = __floats2half2_rn(v.z, v.w);
    }
    for (int i = tid; i < G * C; i += K2_THREADS)
        MTh[(i / C) * HST + (i % C)] = __float2half(d_MT[i]);
    if      (tid < 36) cst[tid] = Ww2[tid];
    else if (tid < 42) cst[tid] = bw2[tid - 36];
    else if (tid < 48) cst[tid] = bw1[tid - 42];
    else if (tid < 54) cst[tid] = gw[tid - 48];
    else if (tid < 60) cst[tid] = betaw[tid - 54];
    else if (tid < 66) cst[tid] = d_bM[tid - 60];

    const int c0 = l, c1 = l + 32, c2 = l + 64;
    float w10[3], w11[3], w12[3], b1c[3], spc[3], btc[3], bp2v[3];
    #pragma unroll
    for (int p = 0; p < 3; p++) {
        int ch = l + 32 * p;
        w10[p] = __ldg(&Wp1[ch]);
        w11[p] = __ldg(&Wp1[C + ch]);
        w12[p] = __ldg(&Wp1[2 * C + ch]);
        b1c[p] = __ldg(&bp1[ch]);
        spc[p] = __ldg(&gp[ch]) * RS;
        btc[p] = __ldg(&betap[ch]);
        bp2v[p] = __ldg(&bp2[ch]);
    }
    const bool hi = (l >= 16);
    const int gc0 = hi ? 1 : 0, gc1 = hi ? 3 : 2, gc2 = hi ? 5 : 4;
    __syncthreads();

    for (int pt = blockIdx.x * PTS + pod; pt < NPTS; pt += K2_PODS) {
        const size_t n = (size_t)pt;

        if (l < 16) {
            int j = __ldg(&refidx[n * S + l]);
            js_[l] = j;
            float cx = __ldg(&coord[n * 3 + 0]);
            float cy = __ldg(&coord[n * 3 + 1]);
            float cz = __ldg(&coord[n * 3 + 2]);
            pos[l * 4 + 0] = __ldg(&coord[(size_t)j * 3 + 0]) - cx;
            pos[l * 4 + 1] = __ldg(&coord[(size_t)j * 3 + 1]) - cy;
            pos[l * 4 + 2] = __ldg(&coord[(size_t)j * 3 + 2]) - cz;
        }
        __syncwarp();

        #pragma unroll
        for (int s = 0; s < 16; s++) {
            float4 pp = *(const float4*)&pos[s * 4];
            #pragma unroll
            for (int p = 0; p < 3; p++) {
                float hv = fmaf(pp.x, w10[p], fmaf(pp.y, w11[p], fmaf(pp.z, w12[p], b1c[p])));
                hv = fmaxf(fmaf(hv, spc[p], btc[p]), 0.0f);
                hs_h[s * HST + l + 32 * p] = __float2half(hv);
            }
        }
        __syncwarp();

        #pragma unroll
        for (int p = 0; p < 3; p++) {
            int idx = l + 32 * p;
            int s = idx / 6, g = idx % 6;
            const uint4* hp = (const uint4*)(hs_h + s * HST);
            const uint4* mp = (const uint4*)(MTh + g * HST);
            __half2 a0 = __float2half2_rn(0.f), a1 = a0;
            #pragma unroll
            for (int i = 0; i < 12; i++) {
                uint4 hu = hp[i], mu = mp[i];
                a0 = __hfma2(h2u(hu.x), h2u(mu.x), a0);
                a1 = __hfma2(h2u(hu.y), h2u(mu.y), a1);
                a0 = __hfma2(h2u(hu.z), h2u(mu.z), a0);
                a1 = __hfma2(h2u(hu.w), h2u(mu.w), a1);
            }
            float2 f0 = __half22float2(a0), f1 = __half22float2(a1);
            float dot = (f0.x + f0.y) + (f1.x + f1.y);
            float kq = __ldg(&d_kW[(size_t)js_[s] * G + g]) - __ldg(&d_qW[n * G + g]);
            float tt = kq + dot + cst[60 + g] + cst[42 + g];
            us[idx] = fmaxf(fmaf(tt, cst[48 + g] * RS, cst[54 + g]), 0.0f);
        }
        __syncwarp();

        if (l < 24) {
            const int q = l / 6, g2 = l % 6;
            float lg[4];
            #pragma unroll
            for (int i = 0; i < 4; i++) {
                int s = q * 4 + i;
                float lv = cst[36 + g2];
                #pragma unroll
                for (int g = 0; g < 6; g++)
                    lv = fmaf(us[s * 6 + g], cst[g * 6 + g2], lv);
                lg[i] = lv;
            }
            float lm = fmaxf(fmaxf(lg[0], lg[1]), fmaxf(lg[2], lg[3]));
            float m1 = fmaxf(lm, __shfl_down_sync(0x00FFFFFF, lm, 12));
            float m  = fmaxf(m1, __shfl_down_sync(0x00FFFFFF, m1, 6));
            m = __shfl_sync(0x00FFFFFF, m, g2);
            float e[4];
            float sm = 0.f;
            #pragma unroll
            for (int i = 0; i < 4; i++) { e[i] = __expf(lg[i] - m); sm += e[i]; }
            float sm1 = sm + __shfl_down_sync(0x00FFFFFF, sm, 12);
            float smt = sm1 + __shfl_down_sync(0x00FFFFFF, sm1, 6);
            float inv = 1.0f / __shfl_sync(0x00FFFFFF, smt, g2);
            float accw = 0.f;
            #pragma unroll
            for (int i = 0; i < 4; i++) {
                int s = q * 4 + i;
                int jp1 = js_[s] + 1;
                float msk = (float)((jp1 > 0) - (jp1 < 0));
                float w = e[i] * inv * msk;
                ws[s * 8 + g2] = w;
                accw += w;
            }
            float a1r = accw + __shfl_down_sync(0x00FFFFFF, accw, 12);
            float at  = a1r + __shfl_down_sync(0x00FFFFFF, a1r, 6);
            if (l < 6) wsum[l] = at;
        }
        __syncwarp();

        u64 HA[3] = {0,0,0}, HB[3] = {0,0,0}, HC[3] = {0,0,0};
        float vs0 = 0.f, vs1 = 0.f, vs2 = 0.f;
        #pragma unroll
        for (int s = 0; s < 16; s++) {
            ulonglong2 w03 = *(const ulonglong2*)&ws[s * 8];
            u64 w45 = *(const u64*)&ws[s * 8 + 4];
            float h0 = __half2float(hs_h[s * HST + c0]);
            float h1 = __half2float(hs_h[s * HST + c1]);
            float h2 = __half2float(hs_h[s * HST + c2]);
            u64 h0d = dup2(h0), h1d = dup2(h1), h2d = dup2(h2);
            HA[0] = fma2(h0d, w03.x, HA[0]);
            HA[1] = fma2(h0d, w03.y, HA[1]);
            HA[2] = fma2(h0d, w45,   HA[2]);
            HB[0] = fma2(h1d, w03.x, HB[0]);
            HB[1] = fma2(h1d, w03.y, HB[1]);
            HB[2] = fma2(h1d, w45,   HB[2]);
            HC[0] = fma2(h2d, w03.x, HC[0]);
            HC[1] = fma2(h2d, w03.y, HC[1]);
            HC[2] = fma2(h2d, w45,   HC[2]);
            float wg0 = hi ? hi2(w03.x) : lo2(w03.x);
            float wg1 = hi ? hi2(w03.y) : lo2(w03.y);
            float wg2 = hi ? hi2(w45)   : lo2(w45);
            int j = js_[s];
            vs0 = fmaf(wg0, __ldg(&d_v[(size_t)j * C + c0]), vs0);
            vs1 = fmaf(wg1, __ldg(&d_v[(size_t)j * C + c1]), vs1);
            vs2 = fmaf(wg2, __ldg(&d_v[(size_t)j * C + c2]), vs2);
        }
        Hs_h[0 * HST + c0] = __float2half(lo2(HA[0]));
        Hs_h[1 * HST + c0] = __float2half(hi2(HA[0]));
        Hs_h[2 * HST + c0] = __float2half(lo2(HA[1]));
        Hs_h[3 * HST + c0] = __float2half(hi2(HA[1]));
        Hs_h[4 * HST + c0] = __float2half(lo2(HA[2]));
        Hs_h[5 * HST + c0] = __float2half(hi2(HA[2]));
        Hs_h[0 * HST + c1] = __float2half(lo2(HB[0]));
        Hs_h[1 * HST + c1] = __float2half(hi2(HB[0]));
        Hs_h[2 * HST + c1] = __float2half(lo2(HB[1]));
        Hs_h[3 * HST + c1] = __float2half(hi2(HB[1]));
        Hs_h[4 * HST + c1] = __float2half(lo2(HB[2]));
        Hs_h[5 * HST + c1] = __float2half(hi2(HB[2]));
        Hs_h[0 * HST + c2] = __float2half(lo2(HC[0]));
        Hs_h[1 * HST + c2] = __float2half(hi2(HC[0]));
        Hs_h[2 * HST + c2] = __float2half(lo2(HC[1]));
        Hs_h[3 * HST + c2] = __float2half(hi2(HC[1]));
        Hs_h[4 * HST + c2] = __float2half(lo2(HC[2]));
        Hs_h[5 * HST + c2] = __float2half(hi2(HC[2]));
        __syncwarp();

        float vsv[3] = {vs0, vs1, vs2};
        int   gcv[3] = {gc0, gc1, gc2};
        #pragma unroll
        for (int p = 0; p < 3; p++) {
            int cc_ = l + 32 * p;
            int gcp = gcv[p];
            const uint4* wp = (const uint4*)(Wp2Th + cc_ * HST);
            const uint4* hp = (const uint4*)(Hs_h + gcp * HST);
            __half2 b0 = __float2half2_rn(0.f), b1 = b0, b2 = b0, b3 = b0;
            #pragma unroll
            for (int i = 0; i < 12; i++) {
                uint4 wu = wp[i], hu = hp[i];
                b0 = __hfma2(h2u(wu.x), h2u(hu.x), b0);
                b1 = __hfma2(h2u(wu.y), h2u(hu.y), b1);
                b2 = __hfma2(h2u(wu.z), h2u(hu.z), b2);
                b3 = __hfma2(h2u(wu.w), h2u(hu.w), b3);
            }
            float2 f0 = __half22float2(b0), f1 = __half22float2(b1);
            float2 f2 = __half22float2(b2), f3 = __half22float2(b3);
            float dot = ((f0.x + f0.y) + (f1.x + f1.y)) + ((f2.x + f2.y) + (f3.x + f3.y));
            out[n * C + cc_] = fmaf(bp2v[p], wsum[gcp], vsv[p]) + dot;
        }
        __syncwarp();
    }
}

// ---------------- host launcher ---------------------------------------------
extern "C" void kernel_launch(void* const* d_in, const int* in_sizes, int n_in,
                              void* d_out, int out_size)
{
    bool dict = (in_sizes[2] == NPTS * S);

    const float* feat  = (const float*)d_in[0];
    const float* coord = (const float*)d_in[1];
    const int*   ref   = (const int*)d_in[dict ? 2 : 24];
    int wb = dict ? 3 : 2;
    const float* Wq    = (const float*)d_in[wb + 0];
    const float* bq    = (const float*)d_in[wb + 1];
    const float* gq    = (const float*)d_in[wb + 2];
    const float* betaq = (const float*)d_in[wb + 3];
    const float* Wk    = (const float*)d_in[wb + 4];
    const float* bk    = (const float*)d_in[wb + 5];
    const float* gk    = (const float*)d_in[wb + 6];
    const float* betak = (const float*)d_in[wb + 7];
    const float* Wv    = (const float*)d_in[wb + 8];
    const float* bv    = (const float*)d_in[wb + 9];
    const float* Wp1   = (const float*)d_in[wb + 10];
    const float* bp1   = (const float*)d_in[wb + 11];
    const float* gp    = (const float*)d_in[wb + 12];
    const float* betap = (const float*)d_in[wb + 13];
    const float* Wp2   = (const float*)d_in[wb + 14];
    const float* bp2   = (const float*)d_in[wb + 15];
    const float* Ww1   = (const float*)d_in[wb + 16];
    const float* bw1   = (const float*)d_in[wb + 17];
    const float* gw    = (const float*)d_in[wb + 18];
    const float* betaw = (const float*)d_in[wb + 19];
    const float* Ww2   = (const float*)d_in[wb + 20];
    const float* bw2   = (const float*)d_in[wb + 21];
    float* out = (float*)d_out;

    cudaFuncSetAttribute(k1_qkv,  cudaFuncAttributeMaxDynamicSharedMemorySize, K1_SMEM);
    cudaFuncSetAttribute(k2_attn, cudaFuncAttributeMaxDynamicSharedMemorySize, K2_SMEM);

    k1_qkv<<<K1_GRID, K1_THREADS, K1_SMEM>>>(
        feat, Wq, bq, gq, betaq, Wk, bk, gk, betak, Wv, bv, Ww1, Wp2, bp2);
    k2_attn<<<K2_GRID, K2_THREADS, K2_SMEM>>>(
        coord, ref, Wp1, bp1, gp, betap, bp2, bw1, gw, betaw, Ww2, bw2, out);
}